// round 6
// baseline (speedup 1.0000x reference)
#include <cuda_runtime.h>

#define DEG2RAD 0.017453292519943295f

// packed per-view interpolation weights {w1, w2}; CHECK_LIST = {0,3,8,20,26,32,36,39}
// tilt_deg(v) = w1*t[i1] + w2*t[i2]  (v==14 special-cased to -15)
__constant__ float2 c_w[40] = {
    {1.0f, 0.0f}, {0.6666666666666667f, 0.3333333333333333f}, {0.33333333333333337f, 0.6666666666666666f},
    {1.0f, 0.0f}, {0.8f, 0.2f}, {0.6f, 0.4f}, {0.4f, 0.6f}, {0.19999999999999996f, 0.8f},
    {1.0f, 0.0f}, {0.9166666666666666f, 0.08333333333333333f}, {0.8333333333333334f, 0.16666666666666666f},
    {0.75f, 0.25f}, {0.6666666666666667f, 0.3333333333333333f}, {0.5833333333333333f, 0.4166666666666667f},
    {0.0f, 0.0f},
    {0.41666666666666663f, 0.5833333333333334f}, {0.33333333333333337f, 0.6666666666666666f}, {0.25f, 0.75f},
    {0.16666666666666663f, 0.8333333333333334f}, {0.08333333333333337f, 0.9166666666666666f},
    {1.0f, 0.0f}, {0.8333333333333334f, 0.16666666666666666f}, {0.6666666666666667f, 0.3333333333333333f},
    {0.5f, 0.5f}, {0.33333333333333337f, 0.6666666666666666f}, {0.16666666666666663f, 0.8333333333333334f},
    {1.0f, 0.0f}, {0.8333333333333334f, 0.16666666666666666f}, {0.6666666666666667f, 0.3333333333333333f},
    {0.5f, 0.5f}, {0.33333333333333337f, 0.6666666666666666f}, {0.16666666666666663f, 0.8333333333333334f},
    {1.0f, 0.0f}, {0.75f, 0.25f}, {0.5f, 0.5f}, {0.25f, 0.75f},
    {1.0f, 0.0f}, {0.6666666666666667f, 0.3333333333333333f}, {0.33333333333333337f, 0.6666666666666666f},
    {1.0f, 0.0f} };

// Per-row computation, fully inlined twice.
__device__ __forceinline__ void compute_row(
    int r,
    const float* __restrict__ rot_angles, const float* __restrict__ mag,
    const float* __restrict__ xyz, const float* __restrict__ tilt_angles,
    const float* __restrict__ offset, float* __restrict__ out)
{
    // 142 rows: marker-major, views inner, skipping (m==1, v<18)
    int m   = (r >= 40) + (r >= 62) + (r >= 102);
    int sub = (m == 0) ? 0 : (m == 1) ? 22 : (m == 2) ? 62 : 102;
    int v   = r - sub;

    int i1 = (v >= 3) + (v >= 8) + (v >= 20) + (v >= 26)
           + (v >= 32) + (v >= 36) + (v >= 39);
    int i2 = (i1 < 7) ? i1 + 1 : 7;

    float t1 = tilt_angles[i1];
    float t2 = tilt_angles[i2];
    float rotd = rot_angles[v];
    float mg_raw = mag[v];
    float2 off = ((const float2*)offset)[v];
    float x = xyz[3 * m + 0];
    float y = xyz[3 * m + 1];
    float z = xyz[3 * m + 2];
    float2 w12 = c_w[v];

    float tilt_deg = fmaf(w12.x, t1, w12.y * t2);
    tilt_deg = (v == 14) ? -15.0f : tilt_deg;

    float tilt = tilt_deg * DEG2RAD;
    float rot  = rotd * DEG2RAD;

    float sr, cr, st, ct;
    __sincosf(rot,  &sr, &cr);
    __sincosf(tilt, &st, &ct);

    float mg = (v == 0) ? 1.0f : mg_raw;
    float ox = (v == 0) ? 0.0f : off.x;
    float oy = (v == 0) ? 0.0f : off.y;

    float mcr = mg * cr;
    float msr = mg * sr;
    float u  = fmaf(mcr * ct, x, fmaf(-msr, y, fmaf(mcr * st, z, ox)));
    float wv = fmaf(msr * ct, x, fmaf( mcr, y, fmaf(msr * st, z, oy)));

    ((float2*)out)[r] = make_float2(u, wv);
}

// 128 threads = 4 warps = exactly one warp per SMSP.
// Lanes 0..13 of warp 0 additionally handle rows 128..141.
__global__ __launch_bounds__(128, 1)
void align_kernel(const float* __restrict__ rot_angles,
                  const float* __restrict__ mag,
                  const float* __restrict__ xyz,
                  const float* __restrict__ tilt_angles,
                  const float* __restrict__ offset,
                  float* __restrict__ out)
{
    int r = threadIdx.x;
    compute_row(r, rot_angles, mag, xyz, tilt_angles, offset, out);
    if (r < 14)
        compute_row(r + 128, rot_angles, mag, xyz, tilt_angles, offset, out);
}

extern "C" void kernel_launch(void* const* d_in, const int* in_sizes, int n_in,
                              void* d_out, int out_size)
{
    const float* rot_angles  = (const float*)d_in[0];
    const float* mag         = (const float*)d_in[1];
    const float* xyz         = (const float*)d_in[2];
    const float* tilt_angles = (const float*)d_in[3];
    const float* offset      = (const float*)d_in[4];
    float* out = (float*)d_out;

    align_kernel<<<1, 128>>>(rot_angles, mag, xyz, tilt_angles, offset, out);
}

// round 7
// speedup vs baseline: 1.1768x; 1.1768x over previous
#include <cuda_runtime.h>

#define DEG2RAD 0.017453292519943295f

// packed per-view interpolation weights {w1, w2}; CHECK_LIST = {0,3,8,20,26,32,36,39}
// tilt_deg(v) = w1*t[i1] + w2*t[i2]  (v==14 special-cased to -15)
__constant__ float2 c_w[40] = {
    {1.0f, 0.0f}, {0.6666666666666667f, 0.3333333333333333f}, {0.33333333333333337f, 0.6666666666666666f},
    {1.0f, 0.0f}, {0.8f, 0.2f}, {0.6f, 0.4f}, {0.4f, 0.6f}, {0.19999999999999996f, 0.8f},
    {1.0f, 0.0f}, {0.9166666666666666f, 0.08333333333333333f}, {0.8333333333333334f, 0.16666666666666666f},
    {0.75f, 0.25f}, {0.6666666666666667f, 0.3333333333333333f}, {0.5833333333333333f, 0.4166666666666667f},
    {0.0f, 0.0f},
    {0.41666666666666663f, 0.5833333333333334f}, {0.33333333333333337f, 0.6666666666666666f}, {0.25f, 0.75f},
    {0.16666666666666663f, 0.8333333333333334f}, {0.08333333333333337f, 0.9166666666666666f},
    {1.0f, 0.0f}, {0.8333333333333334f, 0.16666666666666666f}, {0.6666666666666667f, 0.3333333333333333f},
    {0.5f, 0.5f}, {0.33333333333333337f, 0.6666666666666666f}, {0.16666666666666663f, 0.8333333333333334f},
    {1.0f, 0.0f}, {0.8333333333333334f, 0.16666666666666666f}, {0.6666666666666667f, 0.3333333333333333f},
    {0.5f, 0.5f}, {0.33333333333333337f, 0.6666666666666666f}, {0.16666666666666663f, 0.8333333333333334f},
    {1.0f, 0.0f}, {0.75f, 0.25f}, {0.5f, 0.5f}, {0.25f, 0.75f},
    {1.0f, 0.0f}, {0.6666666666666667f, 0.3333333333333333f}, {0.33333333333333337f, 0.6666666666666666f},
    {1.0f, 0.0f} };

// Per-row computation; fully inlined at each call site so the compiler can
// batch the independent loads of multiple rows for ILP.
__device__ __forceinline__ void compute_row(
    int r,
    const float* __restrict__ rot_angles, const float* __restrict__ mag,
    const float* __restrict__ xyz, const float* __restrict__ tilt_angles,
    const float* __restrict__ offset, float* __restrict__ out)
{
    // 142 rows: marker-major, views inner, skipping (m==1, v<18)
    int m   = (r >= 40) + (r >= 62) + (r >= 102);
    int sub = (m == 0) ? 0 : (m == 1) ? 22 : (m == 2) ? 62 : 102;
    int v   = r - sub;

    int i1 = (v >= 3) + (v >= 8) + (v >= 20) + (v >= 26)
           + (v >= 32) + (v >= 36) + (v >= 39);
    int i2 = (i1 < 7) ? i1 + 1 : 7;

    float t1 = tilt_angles[i1];
    float t2 = tilt_angles[i2];
    float rotd = rot_angles[v];
    float mg_raw = mag[v];
    float2 off = ((const float2*)offset)[v];
    float x = xyz[3 * m + 0];
    float y = xyz[3 * m + 1];
    float z = xyz[3 * m + 2];
    float2 w12 = c_w[v];

    float tilt_deg = fmaf(w12.x, t1, w12.y * t2);
    tilt_deg = (v == 14) ? -15.0f : tilt_deg;

    float tilt = tilt_deg * DEG2RAD;
    float rot  = rotd * DEG2RAD;

    float sr, cr, st, ct;
    __sincosf(rot,  &sr, &cr);
    __sincosf(tilt, &st, &ct);

    float mg = (v == 0) ? 1.0f : mg_raw;
    float ox = (v == 0) ? 0.0f : off.x;
    float oy = (v == 0) ? 0.0f : off.y;

    float mcr = mg * cr;
    float msr = mg * sr;
    float u  = fmaf(mcr * ct, x, fmaf(-msr, y, fmaf(mcr * st, z, ox)));
    float wv = fmaf(msr * ct, x, fmaf( mcr, y, fmaf(msr * st, z, oy)));

    ((float2*)out)[r] = make_float2(u, wv);
}

// 64 threads = 2 warps. Every thread handles rows r and r+64 (independent,
// ILP-overlapped); lanes 0..13 of warp 0 additionally handle rows 128..141.
__global__ __launch_bounds__(64, 1)
void align_kernel(const float* __restrict__ rot_angles,
                  const float* __restrict__ mag,
                  const float* __restrict__ xyz,
                  const float* __restrict__ tilt_angles,
                  const float* __restrict__ offset,
                  float* __restrict__ out)
{
    int r = threadIdx.x;
    compute_row(r,      rot_angles, mag, xyz, tilt_angles, offset, out);
    compute_row(r + 64, rot_angles, mag, xyz, tilt_angles, offset, out);
    if (r < 14)
        compute_row(r + 128, rot_angles, mag, xyz, tilt_angles, offset, out);
}

extern "C" void kernel_launch(void* const* d_in, const int* in_sizes, int n_in,
                              void* d_out, int out_size)
{
    const float* rot_angles  = (const float*)d_in[0];
    const float* mag         = (const float*)d_in[1];
    const float* xyz         = (const float*)d_in[2];
    const float* tilt_angles = (const float*)d_in[3];
    const float* offset      = (const float*)d_in[4];
    float* out = (float*)d_out;

    align_kernel<<<1, 64>>>(rot_angles, mag, xyz, tilt_angles, offset, out);
}